// round 1
// baseline (speedup 1.0000x reference)
#include <cuda_runtime.h>

#define BSZ  1024
#define TLEN 512
#define KDIM 64

__device__ float g_partials[BSZ];

__global__ __launch_bounds__(128) void crf_forward_kernel(
    const float* __restrict__ logits,
    const float* __restrict__ trans,
    const int*   __restrict__ gold,
    const int*   __restrict__ seq_len)
{
    __shared__ float e_sh[2][KDIM];
    __shared__ float shift_sh[2];
    __shared__ float red_sh[2][KDIM];

    const int tid = threadIdx.x;
    const int g   = tid >> 6;        // group 0: warps 0,1 ; group 1: warps 2,3
    const int j   = tid & 63;        // state index
    const int b   = blockIdx.x * 2 + g;

    // Precompute E[j][i] = exp(trans[j][i]) into registers (row j per thread)
    float Erow[KDIM];
    #pragma unroll
    for (int i = 0; i < KDIM; i += 4) {
        float4 tv = *reinterpret_cast<const float4*>(&trans[j * KDIM + i]);
        Erow[i]     = __expf(tv.x);
        Erow[i + 1] = __expf(tv.y);
        Erow[i + 2] = __expf(tv.z);
        Erow[i + 3] = __expf(tv.w);
    }

    const int L    = seq_len[b];
    const int Lo   = seq_len[b ^ 1];
    const int Lmax = max(L, Lo);

    const float* lb = logits + (size_t)b * TLEN * KDIM;
    const int*   gb = gold + b * TLEN;

    // t = 0
    float alpha = lb[j];
    int   gprev = gb[0];
    float first_acc  = (j == gprev) ? alpha : 0.0f;
    float second_acc = 0.0f;

    if (j == 0) shift_sh[g] = alpha;
    __syncthreads();
    float shift = shift_sh[g];

    // prefetch t = 1
    float lg = 0.0f;
    int   gcur = 0;
    if (1 < L) { lg = lb[KDIM + j]; gcur = gb[1]; }

    for (int t = 1; t < Lmax; t++) {
        float e = __expf(alpha - shift);
        e_sh[g][j] = e;
        __syncthreads();                     // e_sh ready

        // prefetch t+1 (hide LDG latency behind the dot)
        float lg_n = 0.0f;
        int   g_n  = 0;
        if (t + 1 < L) {
            lg_n = lb[(size_t)(t + 1) * KDIM + j];
            g_n  = gb[t + 1];
        }

        if (t < L) {
            float s0 = 0.f, s1 = 0.f, s2 = 0.f, s3 = 0.f;
            #pragma unroll
            for (int i = 0; i < KDIM; i += 4) {
                float4 ev = *reinterpret_cast<const float4*>(&e_sh[g][i]);
                s0 = fmaf(Erow[i],     ev.x, s0);
                s1 = fmaf(Erow[i + 1], ev.y, s1);
                s2 = fmaf(Erow[i + 2], ev.z, s2);
                s3 = fmaf(Erow[i + 3], ev.w, s3);
            }
            float s  = (s0 + s1) + (s2 + s3);
            float na = shift + __logf(s) + lg;

            if (j == gcur) first_acc += lg;                       // unary term
            if (j == 0)    second_acc += trans[gprev * KDIM + gcur]; // pairwise term
            alpha = na;
            if (j == 0) shift_sh[g] = na;    // shift for next step = new alpha[0]
        }
        gprev = gcur; gcur = g_n; lg = lg_n;
        __syncthreads();                     // e_sh consumed + shift published
        shift = shift_sh[g];
    }

    // third_b = logsumexp_j(alpha)
    red_sh[g][j] = alpha;
    __syncthreads();
    #pragma unroll
    for (int off = 32; off > 0; off >>= 1) {
        if (j < off) red_sh[g][j] = fmaxf(red_sh[g][j], red_sh[g][j + off]);
        __syncthreads();
    }
    float m = red_sh[g][0];
    __syncthreads();
    red_sh[g][j] = __expf(alpha - m);
    __syncthreads();
    #pragma unroll
    for (int off = 32; off > 0; off >>= 1) {
        if (j < off) red_sh[g][j] += red_sh[g][j + off];
        __syncthreads();
    }
    float third = m + __logf(red_sh[g][0]);
    __syncthreads();

    // reduce first_acc across the 64 threads of the group
    red_sh[g][j] = first_acc;
    __syncthreads();
    #pragma unroll
    for (int off = 32; off > 0; off >>= 1) {
        if (j < off) red_sh[g][j] += red_sh[g][j + off];
        __syncthreads();
    }
    if (j == 0) g_partials[b] = red_sh[g][0] + second_acc - third;
}

__global__ void crf_reduce_kernel(float* __restrict__ out)
{
    __shared__ double sh[256];
    const int t = threadIdx.x;
    double s = (double)g_partials[t]
             + (double)g_partials[t + 256]
             + (double)g_partials[t + 512]
             + (double)g_partials[t + 768];
    sh[t] = s;
    __syncthreads();
    for (int off = 128; off > 0; off >>= 1) {
        if (t < off) sh[t] += sh[t + off];
        __syncthreads();
    }
    if (t == 0) out[0] = (float)(-sh[0] / (double)BSZ);
}

extern "C" void kernel_launch(void* const* d_in, const int* in_sizes, int n_in,
                              void* d_out, int out_size)
{
    const float* logits  = (const float*)d_in[0];
    const float* trans   = (const float*)d_in[1];
    const int*   gold    = (const int*)d_in[2];
    const int*   seq_len = (const int*)d_in[3];

    crf_forward_kernel<<<BSZ / 2, 128>>>(logits, trans, gold, seq_len);
    crf_reduce_kernel<<<1, 256>>>((float*)d_out);
}